// round 7
// baseline (speedup 1.0000x reference)
#include <cuda_runtime.h>
#include <math.h>

#define Bsz   8
#define Tt    16
#define NCc   128
#define S64   68      // padded row stride for 64-wide matrices
#define S128  132     // padded row stride for 128-wide hidden

typedef unsigned long long u64;

// Pre-transposed MLP weights: g_w1T[d][h] = msg_w1[h][d], g_w2T[h][d] = msg_w2[d][h]
__device__ __align__(16) float g_w1T[64 * 128];
__device__ __align__(16) float g_w2T[128 * 64];

__global__ void mg_transpose(const float* __restrict__ w1,
                             const float* __restrict__ w2) {
    int tid = blockIdx.x * blockDim.x + threadIdx.x;
    if (tid < 128 * 64) {
        int h = tid / 64, d = tid % 64;         // w1 is [128][64]
        g_w1T[d * 128 + h] = w1[tid];
        int d2 = tid / 128, h2 = tid % 128;     // w2 is [64][128]
        g_w2T[h2 * 64 + d2] = w2[tid];
    }
}

// ---- packed f32x2 helpers ----
__device__ __forceinline__ u64 dup2(float a) {
    u64 r;
    asm("mov.b64 %0, {%1, %1};" : "=l"(r) : "r"(__float_as_uint(a)));
    return r;
}
__device__ __forceinline__ u64 fma2(u64 a, u64 b, u64 c) {
    u64 d;
    asm("fma.rn.f32x2 %0, %1, %2, %3;" : "=l"(d) : "l"(a), "l"(b), "l"(c));
    return d;
}
__device__ __forceinline__ void up2(u64 v, float& a, float& b) {
    unsigned int x, y;
    asm("mov.b64 {%0, %1}, %2;" : "=r"(x), "=r"(y) : "l"(v));
    a = __uint_as_float(x); b = __uint_as_float(y);
}

// One CTA (128 threads) per (b,c). All state SMEM-resident across the T loop.
__global__ __launch_bounds__(128, 2)
void mg_main(const float* __restrict__ x,     const float* __restrict__ h0,
             const float* __restrict__ W0,    const float* __restrict__ heb0,
             const float* __restrict__ nid,
             const float* __restrict__ injw,  const float* __restrict__ injb,
             const float* __restrict__ b1g,   const float* __restrict__ b2g,
             const float* __restrict__ wdl,   const float* __restrict__ dgl,
             const float* __restrict__ hdl,
             const int*   __restrict__ ipi,   const int*   __restrict__ opi,
             float* __restrict__ out) {
    extern __shared__ float sm[];
    float* sH    = sm;                 // 64*S64
    float* sW0   = sH    + 64 * S64;   // 64*S64
    float* sHeb  = sW0   + 64 * S64;   // 64*S64
    float* sM    = sHeb  + 64 * S64;   // 64*S64
    float* sBuf  = sM    + 64 * S64;   // 64*S128 (Wh with stride S64, then hidden with S128)
    float* sX    = sBuf  + 64 * S128;  // 64
    float* sInjB = sX    + 64;         // 256
    float* sGam  = sInjB + 256;        // 64
    float* sHg   = sGam  + 64;         // 64
    float* sOmWg = sHg   + 64;         // 64
    float* sDecW = sOmWg + 64;         // 64
    float* sB1   = sDecW + 64;         // 128
    float* sB2   = sB1   + 128;        // 64
    __shared__ int sIp[4], sOp[4];

    const int tid = threadIdx.x;
    const int c   = blockIdx.x / Bsz;   // consecutive blocks share c -> L2 reuse of cell params
    const int b   = blockIdx.x % Bsz;
    const long base = (long)(b * NCc + c) * 4096;

    // ---------------- setup ----------------
    if (tid < 64) {
        sGam[tid]  = 0.5f / (1.0f + expf(-dgl[c * 64 + tid]));
        sHg[tid]   = 0.5f / (1.0f + expf(-hdl[c * 64 + tid]));
        sOmWg[tid] = 1.0f - 0.5f / (1.0f + expf(-wdl[c * 64 + tid]));
        sDecW[tid] = 1.0f;
        sB2[tid]   = b2g[tid];
        sX[tid]    = x[((long)(b * Tt + 0) * NCc + c) * 64 + tid];
    }
    sB1[tid] = b1g[tid];
    for (int i = tid; i < 256; i += 128) sInjB[i] = injb[c * 256 + i];
    if (tid < 4) { sIp[tid] = ipi[c * 4 + tid]; sOp[tid] = opi[c * 4 + tid]; }
    for (int idx = tid; idx < 4096; idx += 128) {
        int r = idx >> 6, cl = idx & 63;
        sH[r * S64 + cl]   = h0[base + idx];
        sW0[r * S64 + cl]  = W0[base + idx];
        sHeb[r * S64 + cl] = heb0[base + idx];
    }
    __syncthreads();

    const int ti = tid >> 3, tj = tid & 7;     // 16 x 8 tiling (4x8 tiles)
    const int ri = tid >> 4, rj = tid & 15;    // 8 x 16 tiling (8x8 tiles, MLP1)

    for (int t = 0; t < Tt; ++t) {
        // ===== P1: inject matvec + scatter (thr 0-63) | Wh = pw*W0 + heb (thr 64-127) =====
        if (tid < 64) {
            const int d = tid;
            #pragma unroll
            for (int a = 0; a < 4; a++) {
                const float4* wrow = reinterpret_cast<const float4*>(
                    injw + (long)(c * 256 + a * 64 + d) * 64);
                float acc = sInjB[a * 64 + d];
                #pragma unroll 4
                for (int q = 0; q < 16; q++) {
                    float4 w  = __ldg(wrow + q);
                    float4 xv = *reinterpret_cast<const float4*>(sX + 4 * q);
                    acc = fmaf(w.x, xv.x, acc); acc = fmaf(w.y, xv.y, acc);
                    acc = fmaf(w.z, xv.z, acc); acc = fmaf(w.w, xv.w, acc);
                }
                sH[sIp[a] * S64 + d] += acc;   // column d exclusive to this thread
            }
        } else {
            const int r = tid - 64;
            const float pw = sDecW[r];
            const float4* w0r = reinterpret_cast<const float4*>(sW0 + r * S64);
            const float4* hbr = reinterpret_cast<const float4*>(sHeb + r * S64);
            float4*       whr = reinterpret_cast<float4*>(sBuf + r * S64);
            #pragma unroll 4
            for (int q = 0; q < 16; q++) {
                float4 w = w0r[q], hbv = hbr[q];
                float4 o;
                o.x = fmaf(pw, w.x, hbv.x); o.y = fmaf(pw, w.y, hbv.y);
                o.z = fmaf(pw, w.z, hbv.z); o.w = fmaf(pw, w.w, hbv.w);
                whr[q] = o;
            }
        }
        __syncthreads();

        // ===== P2: matmul-1  m = Wh @ h_in   (4x8 tiles, f32x2) =====
        {
            const int i0 = ti * 4, d0 = tj * 8;
            u64 acc[4][4];
            #pragma unroll
            for (int ii = 0; ii < 4; ii++)
                #pragma unroll
                for (int p = 0; p < 4; p++) acc[ii][p] = 0ULL;

            #pragma unroll 4
            for (int j = 0; j < 64; j += 4) {
                float4 wr[4]; ulonglong2 ha[4], hb[4];
                #pragma unroll
                for (int ii = 0; ii < 4; ii++)
                    wr[ii] = *reinterpret_cast<const float4*>(sBuf + (i0 + ii) * S64 + j);
                #pragma unroll
                for (int jj = 0; jj < 4; jj++) {
                    ha[jj] = *reinterpret_cast<const ulonglong2*>(sH + (j + jj) * S64 + d0);
                    hb[jj] = *reinterpret_cast<const ulonglong2*>(sH + (j + jj) * S64 + d0 + 4);
                }
                #pragma unroll
                for (int ii = 0; ii < 4; ii++) {
                    float w4[4] = {wr[ii].x, wr[ii].y, wr[ii].z, wr[ii].w};
                    #pragma unroll
                    for (int jj = 0; jj < 4; jj++) {
                        u64 wd = dup2(w4[jj]);
                        acc[ii][0] = fma2(wd, ha[jj].x, acc[ii][0]);
                        acc[ii][1] = fma2(wd, ha[jj].y, acc[ii][1]);
                        acc[ii][2] = fma2(wd, hb[jj].x, acc[ii][2]);
                        acc[ii][3] = fma2(wd, hb[jj].y, acc[ii][3]);
                    }
                }
            }
            #pragma unroll
            for (int ii = 0; ii < 4; ii++) {
                ulonglong2 v0; v0.x = acc[ii][0]; v0.y = acc[ii][1];
                ulonglong2 v1; v1.x = acc[ii][2]; v1.y = acc[ii][3];
                *reinterpret_cast<ulonglong2*>(sM + (i0 + ii) * S64 + d0)     = v0;
                *reinterpret_cast<ulonglong2*>(sM + (i0 + ii) * S64 + d0 + 4) = v1;
            }
        }
        __syncthreads();

        // ===== P3: MLP layer 1  hid = tanh(m @ w1T + b1)   (8x8 tiles, f32x2) =====
        {
            const int i0 = ri * 8, h0i = rj * 8;
            u64 acc[8][4];
            #pragma unroll
            for (int ii = 0; ii < 8; ii++)
                #pragma unroll
                for (int p = 0; p < 4; p++) acc[ii][p] = 0ULL;

            #pragma unroll 2
            for (int d = 0; d < 64; d += 4) {
                float4 mv[8]; ulonglong2 wA[4], wB[4];
                #pragma unroll
                for (int ii = 0; ii < 8; ii++)
                    mv[ii] = *reinterpret_cast<const float4*>(sM + (i0 + ii) * S64 + d);
                #pragma unroll
                for (int dd = 0; dd < 4; dd++) {
                    wA[dd] = __ldg(reinterpret_cast<const ulonglong2*>(g_w1T + (d + dd) * 128 + h0i));
                    wB[dd] = __ldg(reinterpret_cast<const ulonglong2*>(g_w1T + (d + dd) * 128 + h0i + 4));
                }
                #pragma unroll
                for (int ii = 0; ii < 8; ii++) {
                    float m4[4] = {mv[ii].x, mv[ii].y, mv[ii].z, mv[ii].w};
                    #pragma unroll
                    for (int dd = 0; dd < 4; dd++) {
                        u64 md = dup2(m4[dd]);
                        acc[ii][0] = fma2(md, wA[dd].x, acc[ii][0]);
                        acc[ii][1] = fma2(md, wA[dd].y, acc[ii][1]);
                        acc[ii][2] = fma2(md, wB[dd].x, acc[ii][2]);
                        acc[ii][3] = fma2(md, wB[dd].y, acc[ii][3]);
                    }
                }
            }
            #pragma unroll
            for (int ii = 0; ii < 8; ii++) {
                float v[8];
                up2(acc[ii][0], v[0], v[1]); up2(acc[ii][1], v[2], v[3]);
                up2(acc[ii][2], v[4], v[5]); up2(acc[ii][3], v[6], v[7]);
                float4 o0, o1;
                o0.x = tanhf(v[0] + sB1[h0i + 0]); o0.y = tanhf(v[1] + sB1[h0i + 1]);
                o0.z = tanhf(v[2] + sB1[h0i + 2]); o0.w = tanhf(v[3] + sB1[h0i + 3]);
                o1.x = tanhf(v[4] + sB1[h0i + 4]); o1.y = tanhf(v[5] + sB1[h0i + 5]);
                o1.z = tanhf(v[6] + sB1[h0i + 6]); o1.w = tanhf(v[7] + sB1[h0i + 7]);
                *reinterpret_cast<float4*>(sBuf + (i0 + ii) * S128 + h0i)     = o0;
                *reinterpret_cast<float4*>(sBuf + (i0 + ii) * S128 + h0i + 4) = o1;
            }
        }
        __syncthreads();

        // ===== P4: MLP layer 2 + gated state update (4x8 tiles, f32x2, sH in place) =====
        {
            const int i0 = ti * 4, d0 = tj * 8;
            u64 acc[4][4];
            #pragma unroll
            for (int ii = 0; ii < 4; ii++)
                #pragma unroll
                for (int p = 0; p < 4; p++) acc[ii][p] = 0ULL;

            #pragma unroll 4
            for (int h = 0; h < 128; h += 4) {
                float4 tv[4]; ulonglong2 wA[4], wB[4];
                #pragma unroll
                for (int ii = 0; ii < 4; ii++)
                    tv[ii] = *reinterpret_cast<const float4*>(sBuf + (i0 + ii) * S128 + h);
                #pragma unroll
                for (int hh = 0; hh < 4; hh++) {
                    wA[hh] = __ldg(reinterpret_cast<const ulonglong2*>(g_w2T + (h + hh) * 64 + d0));
                    wB[hh] = __ldg(reinterpret_cast<const ulonglong2*>(g_w2T + (h + hh) * 64 + d0 + 4));
                }
                #pragma unroll
                for (int ii = 0; ii < 4; ii++) {
                    float t4[4] = {tv[ii].x, tv[ii].y, tv[ii].z, tv[ii].w};
                    #pragma unroll
                    for (int hh = 0; hh < 4; hh++) {
                        u64 td = dup2(t4[hh]);
                        acc[ii][0] = fma2(td, wA[hh].x, acc[ii][0]);
                        acc[ii][1] = fma2(td, wA[hh].y, acc[ii][1]);
                        acc[ii][2] = fma2(td, wB[hh].x, acc[ii][2]);
                        acc[ii][3] = fma2(td, wB[hh].y, acc[ii][3]);
                    }
                }
            }
            #pragma unroll
            for (int ii = 0; ii < 4; ii++) {
                const int i = i0 + ii;
                const float g = sGam[i], omg = 1.0f - g;
                float4 n0 = __ldg(reinterpret_cast<const float4*>(nid + ((long)c * 64 + i) * 64 + d0));
                float4 n1 = __ldg(reinterpret_cast<const float4*>(nid + ((long)c * 64 + i) * 64 + d0 + 4));
                float v[8];
                up2(acc[ii][0], v[0], v[1]); up2(acc[ii][1], v[2], v[3]);
                up2(acc[ii][2], v[4], v[5]); up2(acc[ii][3], v[6], v[7]);
                float4 hc0 = *reinterpret_cast<const float4*>(sH + i * S64 + d0);
                float4 hc1 = *reinterpret_cast<const float4*>(sH + i * S64 + d0 + 4);
                float4 o0, o1;
                o0.x = omg * hc0.x + g * tanhf(v[0] + sB2[d0 + 0] + n0.x);
                o0.y = omg * hc0.y + g * tanhf(v[1] + sB2[d0 + 1] + n0.y);
                o0.z = omg * hc0.z + g * tanhf(v[2] + sB2[d0 + 2] + n0.z);
                o0.w = omg * hc0.w + g * tanhf(v[3] + sB2[d0 + 3] + n0.w);
                o1.x = omg * hc1.x + g * tanhf(v[4] + sB2[d0 + 4] + n1.x);
                o1.y = omg * hc1.y + g * tanhf(v[5] + sB2[d0 + 5] + n1.y);
                o1.z = omg * hc1.z + g * tanhf(v[6] + sB2[d0 + 6] + n1.z);
                o1.w = omg * hc1.w + g * tanhf(v[7] + sB2[d0 + 7] + n1.w);
                *reinterpret_cast<float4*>(sH + i * S64 + d0)     = o0;
                *reinterpret_cast<float4*>(sH + i * S64 + d0 + 4) = o1;
            }
        }
        __syncthreads();

        // ===== P5: readout + hebbian update (f32x2 over d) + pw decay + x prefetch =====
        if (tid < 64) {
            float s = sH[sOp[0] * S64 + tid] + sH[sOp[1] * S64 + tid]
                    + sH[sOp[2] * S64 + tid] + sH[sOp[3] * S64 + tid];
            out[((long)(b * Tt + t) * NCc + c) * 64 + tid] = s * 0.125f;
        }
        {
            const int i0 = ti * 4, j0 = tj * 8;
            // acc[ii][jj] holds a packed pair of partial sums over even/odd d
            u64 acc[4][8];
            #pragma unroll
            for (int ii = 0; ii < 4; ii++)
                #pragma unroll
                for (int jj = 0; jj < 8; jj++) acc[ii][jj] = 0ULL;

            #pragma unroll 4
            for (int dq = 0; dq < 64; dq += 4) {
                ulonglong2 hi[4], hj[8];
                #pragma unroll
                for (int ii = 0; ii < 4; ii++)
                    hi[ii] = *reinterpret_cast<const ulonglong2*>(sH + (i0 + ii) * S64 + dq);
                #pragma unroll
                for (int jj = 0; jj < 8; jj++)
                    hj[jj] = *reinterpret_cast<const ulonglong2*>(sH + (j0 + jj) * S64 + dq);
                #pragma unroll
                for (int ii = 0; ii < 4; ii++)
                    #pragma unroll
                    for (int jj = 0; jj < 8; jj++) {
                        acc[ii][jj] = fma2(hi[ii].x, hj[jj].x, acc[ii][jj]);
                        acc[ii][jj] = fma2(hi[ii].y, hj[jj].y, acc[ii][jj]);
                    }
            }
            #pragma unroll
            for (int ii = 0; ii < 4; ii++) {
                const int i = i0 + ii;
                const float hgv = sHg[i], omh = 1.0f - hgv, sc = hgv * (1.0f / 64.0f);
                float4 e0 = *reinterpret_cast<const float4*>(sHeb + i * S64 + j0);
                float4 e1 = *reinterpret_cast<const float4*>(sHeb + i * S64 + j0 + 4);
                float v[8];
                #pragma unroll
                for (int jj = 0; jj < 8; jj++) {
                    float pa, pb;
                    up2(acc[ii][jj], pa, pb);
                    v[jj] = pa + pb;
                }
                v[0] = omh * e0.x + sc * v[0]; v[1] = omh * e0.y + sc * v[1];
                v[2] = omh * e0.z + sc * v[2]; v[3] = omh * e0.w + sc * v[3];
                v[4] = omh * e1.x + sc * v[4]; v[5] = omh * e1.y + sc * v[5];
                v[6] = omh * e1.z + sc * v[6]; v[7] = omh * e1.w + sc * v[7];
                #pragma unroll
                for (int jj = 0; jj < 8; jj++) if (i == j0 + jj) v[jj] = 0.0f;
                float4 o0 = make_float4(v[0], v[1], v[2], v[3]);
                float4 o1 = make_float4(v[4], v[5], v[6], v[7]);
                *reinterpret_cast<float4*>(sHeb + i * S64 + j0)     = o0;
                *reinterpret_cast<float4*>(sHeb + i * S64 + j0 + 4) = o1;
            }
        }
        if (tid < 64) {
            sDecW[tid] *= sOmWg[tid];
            if (t + 1 < Tt)
                sX[tid] = x[((long)(b * Tt + t + 1) * NCc + c) * 64 + tid];
        }
        __syncthreads();
    }
}

extern "C" void kernel_launch(void* const* d_in, const int* in_sizes, int n_in,
                              void* d_out, int out_size) {
    const float* x    = (const float*)d_in[0];
    const float* h0   = (const float*)d_in[1];
    const float* W0   = (const float*)d_in[2];
    const float* heb0 = (const float*)d_in[3];
    const float* nid  = (const float*)d_in[4];
    const float* w1   = (const float*)d_in[5];
    const float* b1   = (const float*)d_in[6];
    const float* w2   = (const float*)d_in[7];
    const float* b2   = (const float*)d_in[8];
    const float* injw = (const float*)d_in[9];
    const float* injb = (const float*)d_in[10];
    const float* wdl  = (const float*)d_in[11];
    const float* dgl  = (const float*)d_in[12];
    const float* hdl  = (const float*)d_in[13];
    const int*   ipi  = (const int*)d_in[14];
    const int*   opi  = (const int*)d_in[15];
    float* out = (float*)d_out;

    const int smem_floats = 64 * S64 * 4 + 64 * S128 + 64 + 256 + 64 * 4 + 128 + 64;
    const int smem_bytes  = smem_floats * 4;
    cudaFuncSetAttribute(mg_main, cudaFuncAttributeMaxDynamicSharedMemorySize, smem_bytes);

    mg_transpose<<<32, 256>>>(w1, w2);
    mg_main<<<NCc * Bsz, 128, smem_bytes>>>(x, h0, W0, heb0, nid, injw, injb,
                                            b1, b2, wdl, dgl, hdl, ipi, opi, out);
}

// round 8
// speedup vs baseline: 1.3340x; 1.3340x over previous
#include <cuda_runtime.h>
#include <math.h>

#define Bsz 8
#define Tt  16
#define NCc 128

typedef unsigned long long u64;

__device__ __align__(16) float g_w1T[64 * 128];
__device__ __align__(16) float g_w2T[128 * 64];

__global__ void mg_transpose(const float* __restrict__ w1,
                             const float* __restrict__ w2) {
    int tid = blockIdx.x * blockDim.x + threadIdx.x;
    if (tid < 128 * 64) {
        int h = tid / 64, d = tid % 64;
        g_w1T[d * 128 + h] = w1[tid];
        int d2 = tid / 128, h2 = tid % 128;
        g_w2T[h2 * 64 + d2] = w2[tid];
    }
}

__device__ __forceinline__ u64 dup2(float a) {
    u64 r; asm("mov.b64 %0, {%1, %1};" : "=l"(r) : "r"(__float_as_uint(a))); return r;
}
__device__ __forceinline__ u64 fma2(u64 a, u64 b, u64 c) {
    u64 d; asm("fma.rn.f32x2 %0, %1, %2, %3;" : "=l"(d) : "l"(a), "l"(b), "l"(c)); return d;
}
__device__ __forceinline__ void up2(u64 v, float& a, float& b) {
    unsigned int x, y; asm("mov.b64 {%0, %1}, %2;" : "=r"(x), "=r"(y) : "l"(v));
    a = __uint_as_float(x); b = __uint_as_float(y);
}

// XOR chunk swizzle: 16B chunks permuted per row -> conflict-free for drow 1/4/8
__device__ __forceinline__ int pr(int r)           { return (r ^ (r >> 3)) & 7; }
__device__ __forceinline__ int a64(int r, int cq)  { return (r << 6) + ((cq ^ pr(r)) << 2); }
__device__ __forceinline__ int a64s(int r, int c)  { return (r << 6) + (((c >> 2) ^ pr(r)) << 2) + (c & 3); }
__device__ __forceinline__ int a128(int r, int cq) { return (r << 7) + ((cq ^ pr(r)) << 2); }

__global__ __launch_bounds__(128, 2)
void mg_main(const float* __restrict__ x,     const float* __restrict__ h0,
             const float* __restrict__ W0,    const float* __restrict__ heb0,
             const float* __restrict__ nid,
             const float* __restrict__ injw,  const float* __restrict__ injb,
             const float* __restrict__ b1g,   const float* __restrict__ b2g,
             const float* __restrict__ wdl,   const float* __restrict__ dgl,
             const float* __restrict__ hdl,
             const int*   __restrict__ ipi,   const int*   __restrict__ opi,
             float* __restrict__ out) {
    extern __shared__ float sm[];
    float* sH    = sm;               // 4096 swizzled a64
    float* sW0   = sH    + 4096;
    float* sHeb  = sW0   + 4096;
    float* sM    = sHeb  + 4096;
    float* sBuf  = sM    + 4096;     // 8192: Wh (a64) then hidden (a128)
    float* sX    = sBuf  + 8192;
    float* sInjB = sX    + 64;       // 256
    float* sGam  = sInjB + 256;
    float* sHg   = sGam  + 64;
    float* sOmWg = sHg   + 64;
    float* sDecW = sOmWg + 64;
    float* sB1   = sDecW + 64;       // 128
    float* sB2   = sB1   + 128;      // 64
    __shared__ int sIp[4], sOp[4];

    const int tid = threadIdx.x;
    const int c   = blockIdx.x / Bsz;
    const int b   = blockIdx.x % Bsz;
    const long base = (long)(b * NCc + c) * 4096;

    if (tid < 64) {
        sGam[tid]  = 0.5f / (1.0f + expf(-dgl[c * 64 + tid]));
        sHg[tid]   = 0.5f / (1.0f + expf(-hdl[c * 64 + tid]));
        sOmWg[tid] = 1.0f - 0.5f / (1.0f + expf(-wdl[c * 64 + tid]));
        sDecW[tid] = 1.0f;
        sB2[tid]   = b2g[tid];
        sX[tid]    = x[((long)(b * Tt) * NCc + c) * 64 + tid];
    }
    sB1[tid] = b1g[tid];
    for (int i = tid; i < 256; i += 128) sInjB[i] = injb[c * 256 + i];
    if (tid < 4) { sIp[tid] = ipi[c * 4 + tid]; sOp[tid] = opi[c * 4 + tid]; }
    for (int k = tid; k < 1024; k += 128) {          // swizzled fill, 16B chunks
        const int r = k >> 4, cq = k & 15, so = a64(r, cq);
        const long go = base + ((long)k << 2);
        *reinterpret_cast<float4*>(sH   + so) = __ldg(reinterpret_cast<const float4*>(h0   + go));
        *reinterpret_cast<float4*>(sW0  + so) = __ldg(reinterpret_cast<const float4*>(W0   + go));
        *reinterpret_cast<float4*>(sHeb + so) = __ldg(reinterpret_cast<const float4*>(heb0 + go));
    }
    __syncthreads();

    const int ti = tid >> 3, tj = tid & 7;     // 16x8: 4-row x 8-col tiles
    const int ri = tid >> 4, rj = tid & 15;    // 8x16: 8-row x 8-col tiles (MLP1)

    for (int t = 0; t < Tt; ++t) {
        // ===== P1: inject+scatter (thr 0-63) | Wh = pw*W0 + heb (thr 64-127) =====
        if (tid < 64) {
            const int d = tid;
            #pragma unroll
            for (int a = 0; a < 4; a++) {
                const float4* wrow = reinterpret_cast<const float4*>(
                    injw + (long)(c * 256 + a * 64 + d) * 64);
                float acc = sInjB[a * 64 + d];
                #pragma unroll 4
                for (int q = 0; q < 16; q++) {
                    float4 w  = __ldg(wrow + q);
                    float4 xv = *reinterpret_cast<const float4*>(sX + 4 * q);
                    acc = fmaf(w.x, xv.x, acc); acc = fmaf(w.y, xv.y, acc);
                    acc = fmaf(w.z, xv.z, acc); acc = fmaf(w.w, xv.w, acc);
                }
                sH[a64s(sIp[a], d)] += acc;
            }
        } else {
            // elementwise on identically-swizzled arrays: linear chunk walk
            for (int k = tid - 64; k < 1024; k += 64) {
                const float pw = sDecW[k >> 4];
                const int o = k << 2;
                float4 w = *reinterpret_cast<const float4*>(sW0 + o);
                float4 hb = *reinterpret_cast<const float4*>(sHeb + o);
                float4 v;
                v.x = fmaf(pw, w.x, hb.x); v.y = fmaf(pw, w.y, hb.y);
                v.z = fmaf(pw, w.z, hb.z); v.w = fmaf(pw, w.w, hb.w);
                *reinterpret_cast<float4*>(sBuf + o) = v;
            }
        }
        __syncthreads();

        // ===== P2: m = Wh @ h_in  (4x8 tiles, f32x2) =====
        {
            const int i0 = ti * 4, c0 = tj * 2;
            u64 acc[4][4];
            #pragma unroll
            for (int ii = 0; ii < 4; ii++) { acc[ii][0]=acc[ii][1]=acc[ii][2]=acc[ii][3]=0ULL; }
            #pragma unroll 4
            for (int j = 0; j < 64; j += 4) {
                float4 wr[4]; ulonglong2 hv[4][2];
                #pragma unroll
                for (int ii = 0; ii < 4; ii++)
                    wr[ii] = *reinterpret_cast<const float4*>(sBuf + a64(i0 + ii, j >> 2));
                #pragma unroll
                for (int jj = 0; jj < 4; jj++) {
                    const int r = j + jj, rb = r << 6, p = pr(r);
                    hv[jj][0] = *reinterpret_cast<const ulonglong2*>(sH + rb + ((c0 ^ p) << 2));
                    hv[jj][1] = *reinterpret_cast<const ulonglong2*>(sH + rb + (((c0 + 1) ^ p) << 2));
                }
                #pragma unroll
                for (int ii = 0; ii < 4; ii++) {
                    const float* wf = reinterpret_cast<const float*>(&wr[ii]);
                    #pragma unroll
                    for (int jj = 0; jj < 4; jj++) {
                        u64 wd = dup2(wf[jj]);
                        acc[ii][0] = fma2(wd, hv[jj][0].x, acc[ii][0]);
                        acc[ii][1] = fma2(wd, hv[jj][0].y, acc[ii][1]);
                        acc[ii][2] = fma2(wd, hv[jj][1].x, acc[ii][2]);
                        acc[ii][3] = fma2(wd, hv[jj][1].y, acc[ii][3]);
                    }
                }
            }
            #pragma unroll
            for (int ii = 0; ii < 4; ii++) {
                const int r = i0 + ii, rb = r << 6, p = pr(r);
                ulonglong2 v0; v0.x = acc[ii][0]; v0.y = acc[ii][1];
                ulonglong2 v1; v1.x = acc[ii][2]; v1.y = acc[ii][3];
                *reinterpret_cast<ulonglong2*>(sM + rb + ((c0 ^ p) << 2))       = v0;
                *reinterpret_cast<ulonglong2*>(sM + rb + (((c0 + 1) ^ p) << 2)) = v1;
            }
        }
        __syncthreads();

        // ===== P3: hidden = tanh(m @ w1T + b1)  (8x8 tiles, f32x2) =====
        {
            const int i0 = ri * 8, h0i = rj * 8, hc0 = rj * 2;
            u64 acc[8][4];
            #pragma unroll
            for (int ii = 0; ii < 8; ii++) { acc[ii][0]=acc[ii][1]=acc[ii][2]=acc[ii][3]=0ULL; }
            #pragma unroll 2
            for (int d = 0; d < 64; d += 4) {
                float4 mv[8]; ulonglong2 wA[4], wB[4];
                #pragma unroll
                for (int ii = 0; ii < 8; ii++)
                    mv[ii] = *reinterpret_cast<const float4*>(sM + a64(i0 + ii, d >> 2));
                #pragma unroll
                for (int dd = 0; dd < 4; dd++) {
                    wA[dd] = __ldg(reinterpret_cast<const ulonglong2*>(g_w1T + (d + dd) * 128 + h0i));
                    wB[dd] = __ldg(reinterpret_cast<const ulonglong2*>(g_w1T + (d + dd) * 128 + h0i + 4));
                }
                #pragma unroll
                for (int ii = 0; ii < 8; ii++) {
                    const float* mf = reinterpret_cast<const float*>(&mv[ii]);
                    #pragma unroll
                    for (int dd = 0; dd < 4; dd++) {
                        u64 md = dup2(mf[dd]);
                        acc[ii][0] = fma2(md, wA[dd].x, acc[ii][0]);
                        acc[ii][1] = fma2(md, wA[dd].y, acc[ii][1]);
                        acc[ii][2] = fma2(md, wB[dd].x, acc[ii][2]);
                        acc[ii][3] = fma2(md, wB[dd].y, acc[ii][3]);
                    }
                }
            }
            #pragma unroll
            for (int ii = 0; ii < 8; ii++) {
                const int r = i0 + ii, rb = r << 7, p = pr(r);
                float v[8];
                up2(acc[ii][0], v[0], v[1]); up2(acc[ii][1], v[2], v[3]);
                up2(acc[ii][2], v[4], v[5]); up2(acc[ii][3], v[6], v[7]);
                float4 o0, o1;
                o0.x = tanhf(v[0] + sB1[h0i + 0]); o0.y = tanhf(v[1] + sB1[h0i + 1]);
                o0.z = tanhf(v[2] + sB1[h0i + 2]); o0.w = tanhf(v[3] + sB1[h0i + 3]);
                o1.x = tanhf(v[4] + sB1[h0i + 4]); o1.y = tanhf(v[5] + sB1[h0i + 5]);
                o1.z = tanhf(v[6] + sB1[h0i + 6]); o1.w = tanhf(v[7] + sB1[h0i + 7]);
                *reinterpret_cast<float4*>(sBuf + rb + ((hc0 ^ p) << 2))       = o0;
                *reinterpret_cast<float4*>(sBuf + rb + (((hc0 + 1) ^ p) << 2)) = o1;
            }
        }
        __syncthreads();

        // ===== P4: MLP2 + gated update  (4x8 tiles, f32x2, sH in place) =====
        {
            const int i0 = ti * 4, d0 = tj * 8, c0 = tj * 2;
            u64 acc[4][4];
            #pragma unroll
            for (int ii = 0; ii < 4; ii++) { acc[ii][0]=acc[ii][1]=acc[ii][2]=acc[ii][3]=0ULL; }
            #pragma unroll 4
            for (int h = 0; h < 128; h += 4) {
                float4 tv[4]; ulonglong2 wA[4], wB[4];
                #pragma unroll
                for (int ii = 0; ii < 4; ii++)
                    tv[ii] = *reinterpret_cast<const float4*>(sBuf + a128(i0 + ii, h >> 2));
                #pragma unroll
                for (int hh = 0; hh < 4; hh++) {
                    wA[hh] = __ldg(reinterpret_cast<const ulonglong2*>(g_w2T + (h + hh) * 64 + d0));
                    wB[hh] = __ldg(reinterpret_cast<const ulonglong2*>(g_w2T + (h + hh) * 64 + d0 + 4));
                }
                #pragma unroll
                for (int ii = 0; ii < 4; ii++) {
                    const float* tf = reinterpret_cast<const float*>(&tv[ii]);
                    #pragma unroll
                    for (int hh = 0; hh < 4; hh++) {
                        u64 td = dup2(tf[hh]);
                        acc[ii][0] = fma2(td, wA[hh].x, acc[ii][0]);
                        acc[ii][1] = fma2(td, wA[hh].y, acc[ii][1]);
                        acc[ii][2] = fma2(td, wB[hh].x, acc[ii][2]);
                        acc[ii][3] = fma2(td, wB[hh].y, acc[ii][3]);
                    }
                }
            }
            #pragma unroll
            for (int ii = 0; ii < 4; ii++) {
                const int i = i0 + ii, rb = i << 6, p = pr(i);
                const int oA = rb + ((c0 ^ p) << 2), oB = rb + (((c0 + 1) ^ p) << 2);
                const float g = sGam[i], omg = 1.0f - g;
                float4 n0 = __ldg(reinterpret_cast<const float4*>(nid + ((long)c * 64 + i) * 64 + d0));
                float4 n1 = __ldg(reinterpret_cast<const float4*>(nid + ((long)c * 64 + i) * 64 + d0 + 4));
                float v[8];
                up2(acc[ii][0], v[0], v[1]); up2(acc[ii][1], v[2], v[3]);
                up2(acc[ii][2], v[4], v[5]); up2(acc[ii][3], v[6], v[7]);
                float4 hc0 = *reinterpret_cast<const float4*>(sH + oA);
                float4 hc1 = *reinterpret_cast<const float4*>(sH + oB);
                float4 o0, o1;
                o0.x = omg * hc0.x + g * tanhf(v[0] + sB2[d0 + 0] + n0.x);
                o0.y = omg * hc0.y + g * tanhf(v[1] + sB2[d0 + 1] + n0.y);
                o0.z = omg * hc0.z + g * tanhf(v[2] + sB2[d0 + 2] + n0.z);
                o0.w = omg * hc0.w + g * tanhf(v[3] + sB2[d0 + 3] + n0.w);
                o1.x = omg * hc1.x + g * tanhf(v[4] + sB2[d0 + 4] + n1.x);
                o1.y = omg * hc1.y + g * tanhf(v[5] + sB2[d0 + 5] + n1.y);
                o1.z = omg * hc1.z + g * tanhf(v[6] + sB2[d0 + 6] + n1.z);
                o1.w = omg * hc1.w + g * tanhf(v[7] + sB2[d0 + 7] + n1.w);
                *reinterpret_cast<float4*>(sH + oA) = o0;
                *reinterpret_cast<float4*>(sH + oB) = o1;
            }
        }
        __syncthreads();

        // ===== P5: readout + hebbian (f32x2 over d) + decay + x prefetch =====
        if (tid < 64) {
            float s = sH[a64s(sOp[0], tid)] + sH[a64s(sOp[1], tid)]
                    + sH[a64s(sOp[2], tid)] + sH[a64s(sOp[3], tid)];
            out[((long)(b * Tt + t) * NCc + c) * 64 + tid] = s * 0.125f;
        }
        {
            const int i0 = ti * 4, j0 = tj * 8, c0 = tj * 2;
            u64 acc[4][8];
            #pragma unroll
            for (int ii = 0; ii < 4; ii++)
                #pragma unroll
                for (int jj = 0; jj < 8; jj++) acc[ii][jj] = 0ULL;
            #pragma unroll 4
            for (int dq = 0; dq < 64; dq += 4) {
                ulonglong2 hi[4], hj[8];
                #pragma unroll
                for (int ii = 0; ii < 4; ii++)
                    hi[ii] = *reinterpret_cast<const ulonglong2*>(sH + a64(i0 + ii, dq >> 2));
                #pragma unroll
                for (int jj = 0; jj < 8; jj++)
                    hj[jj] = *reinterpret_cast<const ulonglong2*>(sH + a64(j0 + jj, dq >> 2));
                #pragma unroll
                for (int ii = 0; ii < 4; ii++)
                    #pragma unroll
                    for (int jj = 0; jj < 8; jj++) {
                        acc[ii][jj] = fma2(hi[ii].x, hj[jj].x, acc[ii][jj]);
                        acc[ii][jj] = fma2(hi[ii].y, hj[jj].y, acc[ii][jj]);
                    }
            }
            #pragma unroll
            for (int ii = 0; ii < 4; ii++) {
                const int i = i0 + ii, rb = i << 6, p = pr(i);
                const int oA = rb + ((c0 ^ p) << 2), oB = rb + (((c0 + 1) ^ p) << 2);
                const float hgv = sHg[i], omh = 1.0f - hgv, sc = hgv * (1.0f / 64.0f);
                float4 e0 = *reinterpret_cast<const float4*>(sHeb + oA);
                float4 e1 = *reinterpret_cast<const float4*>(sHeb + oB);
                float v[8];
                #pragma unroll
                for (int jj = 0; jj < 8; jj++) { float pa, pb; up2(acc[ii][jj], pa, pb); v[jj] = pa + pb; }
                v[0] = omh * e0.x + sc * v[0]; v[1] = omh * e0.y + sc * v[1];
                v[2] = omh * e0.z + sc * v[2]; v[3] = omh * e0.w + sc * v[3];
                v[4] = omh * e1.x + sc * v[4]; v[5] = omh * e1.y + sc * v[5];
                v[6] = omh * e1.z + sc * v[6]; v[7] = omh * e1.w + sc * v[7];
                #pragma unroll
                for (int jj = 0; jj < 8; jj++) if (i == j0 + jj) v[jj] = 0.0f;
                *reinterpret_cast<float4*>(sHeb + oA) = make_float4(v[0], v[1], v[2], v[3]);
                *reinterpret_cast<float4*>(sHeb + oB) = make_float4(v[4], v[5], v[6], v[7]);
            }
        }
        if (tid < 64) {
            sDecW[tid] *= sOmWg[tid];
            if (t + 1 < Tt)
                sX[tid] = x[((long)(b * Tt + t + 1) * NCc + c) * 64 + tid];
        }
        __syncthreads();
    }
}

extern "C" void kernel_launch(void* const* d_in, const int* in_sizes, int n_in,
                              void* d_out, int out_size) {
    const float* x    = (const float*)d_in[0];
    const float* h0   = (const float*)d_in[1];
    const float* W0   = (const float*)d_in[2];
    const float* heb0 = (const float*)d_in[3];
    const float* nid  = (const float*)d_in[4];
    const float* w1   = (const float*)d_in[5];
    const float* b1   = (const float*)d_in[6];
    const float* w2   = (const float*)d_in[7];
    const float* b2   = (const float*)d_in[8];
    const float* injw = (const float*)d_in[9];
    const float* injb = (const float*)d_in[10];
    const float* wdl  = (const float*)d_in[11];
    const float* dgl  = (const float*)d_in[12];
    const float* hdl  = (const float*)d_in[13];
    const int*   ipi  = (const int*)d_in[14];
    const int*   opi  = (const int*)d_in[15];
    float* out = (float*)d_out;

    const int smem_bytes = (4096 * 4 + 8192 + 64 + 256 + 64 * 4 + 128 + 64) * 4;
    cudaFuncSetAttribute(mg_main, cudaFuncAttributeMaxDynamicSharedMemorySize, smem_bytes);

    mg_transpose<<<32, 256>>>(w1, w2);
    mg_main<<<NCc * Bsz, 128, smem_bytes>>>(x, h0, W0, heb0, nid, injw, injb,
                                            b1, b2, wdl, dgl, hdl, ipi, opi, out);
}

// round 9
// speedup vs baseline: 1.8554x; 1.3909x over previous
#include <cuda_runtime.h>
#include <math.h>

#define Bsz 8
#define Tt  16
#define NCc 128

typedef unsigned long long u64;

__device__ __align__(16) float g_w1T[64 * 128];
__device__ __align__(16) float g_w2T[128 * 64];
__device__ __align__(16) float g_inj[Bsz * Tt * NCc * 256];   // precomputed injections

__global__ void mg_transpose(const float* __restrict__ w1,
                             const float* __restrict__ w2) {
    int tid = blockIdx.x * blockDim.x + threadIdx.x;
    if (tid < 128 * 64) {
        int h = tid / 64, d = tid % 64;
        g_w1T[d * 128 + h] = w1[tid];
        int d2 = tid / 128, h2 = tid % 128;
        g_w2T[h2 * 64 + d2] = w2[tid];
    }
}

// Precompute inj[b,t,c,k] = injb[c,k] + sum_d injw[c,k,d] * x[b,t,c,d]
__global__ __launch_bounds__(256) void mg_inject(const float* __restrict__ x,
                                                 const float* __restrict__ injw,
                                                 const float* __restrict__ injb) {
    const int c = blockIdx.x, k = threadIdx.x;
    __shared__ float sx[64];
    float4 wv[16];
    const float4* wrow = reinterpret_cast<const float4*>(injw + (long)(c * 256 + k) * 64);
    #pragma unroll
    for (int q = 0; q < 16; q++) wv[q] = __ldg(wrow + q);
    const float bias = injb[c * 256 + k];
    for (int bt = 0; bt < Bsz * Tt; bt++) {
        if (k < 64) sx[k] = x[((long)bt * NCc + c) * 64 + k];
        __syncthreads();
        float acc = bias;
        #pragma unroll
        for (int q = 0; q < 16; q++) {
            float4 xv = *reinterpret_cast<const float4*>(sx + 4 * q);
            acc = fmaf(wv[q].x, xv.x, acc); acc = fmaf(wv[q].y, xv.y, acc);
            acc = fmaf(wv[q].z, xv.z, acc); acc = fmaf(wv[q].w, xv.w, acc);
        }
        g_inj[((long)bt * NCc + c) * 256 + k] = acc;
        __syncthreads();
    }
}

__device__ __forceinline__ u64 dup2(float a) {
    u64 r; asm("mov.b64 %0, {%1, %1};" : "=l"(r) : "r"(__float_as_uint(a))); return r;
}
__device__ __forceinline__ u64 fma2(u64 a, u64 b, u64 c) {
    u64 d; asm("fma.rn.f32x2 %0, %1, %2, %3;" : "=l"(d) : "l"(a), "l"(b), "l"(c)); return d;
}
__device__ __forceinline__ void up2(u64 v, float& a, float& b) {
    unsigned int x, y; asm("mov.b64 {%0, %1}, %2;" : "=r"(x), "=r"(y) : "l"(v));
    a = __uint_as_float(x); b = __uint_as_float(y);
}

// XOR chunk swizzle (16B chunks permuted per row)
__device__ __forceinline__ int pr(int r)           { return (r ^ (r >> 3)) & 7; }
__device__ __forceinline__ int a64(int r, int cq)  { return (r << 6) + ((cq ^ pr(r)) << 2); }
__device__ __forceinline__ int a64s(int r, int c)  { return (r << 6) + (((c >> 2) ^ pr(r)) << 2) + (c & 3); }
__device__ __forceinline__ int a128(int r, int cq) { return (r << 7) + ((cq ^ pr(r)) << 2); }

__global__ __launch_bounds__(256, 2)
void mg_main(const float* __restrict__ h0,    const float* __restrict__ W0,
             const float* __restrict__ heb0,  const float* __restrict__ nid,
             const float* __restrict__ wdl,   const float* __restrict__ dgl,
             const float* __restrict__ hdl,   const float* __restrict__ b1g,
             const float* __restrict__ b2g,
             const int*   __restrict__ ipi,   const int*   __restrict__ opi,
             float* __restrict__ out) {
    extern __shared__ float sm[];
    float* sH    = sm;               // 4096 (a64 swizzled)
    float* sW0   = sH    + 4096;
    float* sHeb  = sW0   + 4096;
    float* sM    = sHeb  + 4096;
    float* sBuf  = sM    + 4096;     // 8192: Wh (a64) then hidden (a128)
    float* sGam  = sBuf  + 8192;     // 64
    float* sHg   = sGam  + 64;
    float* sOmWg = sHg   + 64;
    float* sDecW = sOmWg + 64;
    float* sB1   = sDecW + 64;       // 128
    float* sB2   = sB1   + 128;      // 64
    __shared__ int sIp[4], sOp[4];

    const int tid = threadIdx.x;
    const int c   = blockIdx.x / Bsz;
    const int b   = blockIdx.x % Bsz;
    const long base = (long)(b * NCc + c) * 4096;

    if (tid < 64) {
        sGam[tid]  = 0.5f / (1.0f + expf(-dgl[c * 64 + tid]));
        sHg[tid]   = 0.5f / (1.0f + expf(-hdl[c * 64 + tid]));
        sOmWg[tid] = 1.0f - 0.5f / (1.0f + expf(-wdl[c * 64 + tid]));
        sDecW[tid] = 1.0f;
        sB2[tid]   = b2g[tid];
    }
    if (tid < 128) sB1[tid] = b1g[tid];
    if (tid < 4) { sIp[tid] = ipi[c * 4 + tid]; sOp[tid] = opi[c * 4 + tid]; }
    for (int k = tid; k < 1024; k += 256) {       // swizzled fill, 16B chunks
        const int r = k >> 4, cq = k & 15, so = a64(r, cq);
        const long go = base + ((long)k << 2);
        *reinterpret_cast<float4*>(sH   + so) = __ldg(reinterpret_cast<const float4*>(h0   + go));
        *reinterpret_cast<float4*>(sW0  + so) = __ldg(reinterpret_cast<const float4*>(W0   + go));
        *reinterpret_cast<float4*>(sHeb + so) = __ldg(reinterpret_cast<const float4*>(heb0 + go));
    }
    __syncthreads();

    // warp-block mapping
    const int wid = tid >> 5, lane = tid & 31;
    const int lr = lane >> 2, lc = lane & 3;
    const int r0   = (wid & 1) * 32 + lr * 4;        // 4 output rows (P2/P3/P4/P5)
    const int cb   = (wid >> 1) * 16;                // 16-col block (P2/P4/P5)
    const int c0   = cb + lc * 4;                    // 4 cols
    const int cq0  = c0 >> 2;                        // chunk idx (64-wide)
    const int p3c0 = (wid >> 1) * 32 + lc * 8;       // 8 cols (P3, 128-wide)
    const int p3cq = p3c0 >> 2;

    for (int t = 0; t < Tt; ++t) {
        // ===== P1: Wh = pw*W0 + heb (all threads) | scatter inj (thr<64) =====
        for (int k = tid; k < 1024; k += 256) {
            const float pw = sDecW[k >> 4];
            const int o = k << 2;
            float4 w = *reinterpret_cast<const float4*>(sW0 + o);
            float4 hb = *reinterpret_cast<const float4*>(sHeb + o);
            float4 v;
            v.x = fmaf(pw, w.x, hb.x); v.y = fmaf(pw, w.y, hb.y);
            v.z = fmaf(pw, w.z, hb.z); v.w = fmaf(pw, w.w, hb.w);
            *reinterpret_cast<float4*>(sBuf + o) = v;
        }
        if (tid < 64) {
            const long ib = ((long)(b * Tt + t) * NCc + c) * 256 + tid;
            #pragma unroll
            for (int a = 0; a < 4; a++)
                sH[a64s(sIp[a], tid)] += __ldg(g_inj + ib + a * 64);
        }
        __syncthreads();

        // ===== P2: m = Wh @ h_in  (4x4 tiles) =====
        {
            u64 acc[4][2];
            #pragma unroll
            for (int ii = 0; ii < 4; ii++) { acc[ii][0] = acc[ii][1] = 0ULL; }
            #pragma unroll 4
            for (int j = 0; j < 64; j += 4) {
                float4 wr[4]; ulonglong2 hv[4];
                #pragma unroll
                for (int ii = 0; ii < 4; ii++)
                    wr[ii] = *reinterpret_cast<const float4*>(sBuf + a64(r0 + ii, j >> 2));
                #pragma unroll
                for (int jj = 0; jj < 4; jj++)
                    hv[jj] = *reinterpret_cast<const ulonglong2*>(sH + a64(j + jj, cq0));
                #pragma unroll
                for (int ii = 0; ii < 4; ii++) {
                    const float* wf = reinterpret_cast<const float*>(&wr[ii]);
                    #pragma unroll
                    for (int jj = 0; jj < 4; jj++) {
                        u64 wd = dup2(wf[jj]);
                        acc[ii][0] = fma2(wd, hv[jj].x, acc[ii][0]);
                        acc[ii][1] = fma2(wd, hv[jj].y, acc[ii][1]);
                    }
                }
            }
            #pragma unroll
            for (int ii = 0; ii < 4; ii++) {
                ulonglong2 v; v.x = acc[ii][0]; v.y = acc[ii][1];
                *reinterpret_cast<ulonglong2*>(sM + a64(r0 + ii, cq0)) = v;
            }
        }
        __syncthreads();

        // ===== P3: hidden = tanh(m @ w1T + b1)  (4x8 tiles) =====
        {
            u64 acc[4][4];
            #pragma unroll
            for (int ii = 0; ii < 4; ii++) { acc[ii][0]=acc[ii][1]=acc[ii][2]=acc[ii][3]=0ULL; }
            #pragma unroll 4
            for (int d = 0; d < 64; d += 4) {
                float4 mv[4]; ulonglong2 wA[4], wB[4];
                #pragma unroll
                for (int ii = 0; ii < 4; ii++)
                    mv[ii] = *reinterpret_cast<const float4*>(sM + a64(r0 + ii, d >> 2));
                #pragma unroll
                for (int dd = 0; dd < 4; dd++) {
                    wA[dd] = __ldg(reinterpret_cast<const ulonglong2*>(g_w1T + (d + dd) * 128 + p3c0));
                    wB[dd] = __ldg(reinterpret_cast<const ulonglong2*>(g_w1T + (d + dd) * 128 + p3c0 + 4));
                }
                #pragma unroll
                for (int ii = 0; ii < 4; ii++) {
                    const float* mf = reinterpret_cast<const float*>(&mv[ii]);
                    #pragma unroll
                    for (int dd = 0; dd < 4; dd++) {
                        u64 md = dup2(mf[dd]);
                        acc[ii][0] = fma2(md, wA[dd].x, acc[ii][0]);
                        acc[ii][1] = fma2(md, wA[dd].y, acc[ii][1]);
                        acc[ii][2] = fma2(md, wB[dd].x, acc[ii][2]);
                        acc[ii][3] = fma2(md, wB[dd].y, acc[ii][3]);
                    }
                }
            }
            #pragma unroll
            for (int ii = 0; ii < 4; ii++) {
                const int r = r0 + ii;
                float v[8];
                up2(acc[ii][0], v[0], v[1]); up2(acc[ii][1], v[2], v[3]);
                up2(acc[ii][2], v[4], v[5]); up2(acc[ii][3], v[6], v[7]);
                float4 o0, o1;
                o0.x = tanhf(v[0] + sB1[p3c0 + 0]); o0.y = tanhf(v[1] + sB1[p3c0 + 1]);
                o0.z = tanhf(v[2] + sB1[p3c0 + 2]); o0.w = tanhf(v[3] + sB1[p3c0 + 3]);
                o1.x = tanhf(v[4] + sB1[p3c0 + 4]); o1.y = tanhf(v[5] + sB1[p3c0 + 5]);
                o1.z = tanhf(v[6] + sB1[p3c0 + 6]); o1.w = tanhf(v[7] + sB1[p3c0 + 7]);
                *reinterpret_cast<float4*>(sBuf + a128(r, p3cq))     = o0;
                *reinterpret_cast<float4*>(sBuf + a128(r, p3cq + 1)) = o1;
            }
        }
        __syncthreads();

        // ===== P4: MLP2 + gated update  (4x4 tiles, sH in place) =====
        {
            u64 acc[4][2];
            #pragma unroll
            for (int ii = 0; ii < 4; ii++) { acc[ii][0] = acc[ii][1] = 0ULL; }
            #pragma unroll 4
            for (int h = 0; h < 128; h += 4) {
                float4 tv[4]; ulonglong2 wv[4];
                #pragma unroll
                for (int ii = 0; ii < 4; ii++)
                    tv[ii] = *reinterpret_cast<const float4*>(sBuf + a128(r0 + ii, h >> 2));
                #pragma unroll
                for (int hh = 0; hh < 4; hh++)
                    wv[hh] = __ldg(reinterpret_cast<const ulonglong2*>(g_w2T + (h + hh) * 64 + c0));
                #pragma unroll
                for (int ii = 0; ii < 4; ii++) {
                    const float* tf = reinterpret_cast<const float*>(&tv[ii]);
                    #pragma unroll
                    for (int hh = 0; hh < 4; hh++) {
                        u64 td = dup2(tf[hh]);
                        acc[ii][0] = fma2(td, wv[hh].x, acc[ii][0]);
                        acc[ii][1] = fma2(td, wv[hh].y, acc[ii][1]);
                    }
                }
            }
            #pragma unroll
            for (int ii = 0; ii < 4; ii++) {
                const int i = r0 + ii, o = a64(i, cq0);
                const float g = sGam[i], omg = 1.0f - g;
                float4 nv = __ldg(reinterpret_cast<const float4*>(nid + ((long)c * 64 + i) * 64 + c0));
                float v[4];
                up2(acc[ii][0], v[0], v[1]); up2(acc[ii][1], v[2], v[3]);
                float4 hc = *reinterpret_cast<const float4*>(sH + o);
                float4 ov;
                ov.x = omg * hc.x + g * tanhf(v[0] + sB2[c0 + 0] + nv.x);
                ov.y = omg * hc.y + g * tanhf(v[1] + sB2[c0 + 1] + nv.y);
                ov.z = omg * hc.z + g * tanhf(v[2] + sB2[c0 + 2] + nv.z);
                ov.w = omg * hc.w + g * tanhf(v[3] + sB2[c0 + 3] + nv.w);
                *reinterpret_cast<float4*>(sH + o) = ov;
            }
        }
        __syncthreads();

        // ===== P5: readout + hebbian (4x4 tiles, f32x2 over d) + decay =====
        if (tid < 64) {
            float s = sH[a64s(sOp[0], tid)] + sH[a64s(sOp[1], tid)]
                    + sH[a64s(sOp[2], tid)] + sH[a64s(sOp[3], tid)];
            out[((long)(b * Tt + t) * NCc + c) * 64 + tid] = s * 0.125f;
        }
        {
            u64 acc[4][4];
            #pragma unroll
            for (int ii = 0; ii < 4; ii++) { acc[ii][0]=acc[ii][1]=acc[ii][2]=acc[ii][3]=0ULL; }
            #pragma unroll 4
            for (int dq = 0; dq < 64; dq += 4) {
                ulonglong2 hi[4], hj[4];
                #pragma unroll
                for (int ii = 0; ii < 4; ii++)
                    hi[ii] = *reinterpret_cast<const ulonglong2*>(sH + a64(r0 + ii, dq >> 2));
                #pragma unroll
                for (int jj = 0; jj < 4; jj++)
                    hj[jj] = *reinterpret_cast<const ulonglong2*>(sH + a64(c0 + jj, dq >> 2));
                #pragma unroll
                for (int ii = 0; ii < 4; ii++)
                    #pragma unroll
                    for (int jj = 0; jj < 4; jj++) {
                        acc[ii][jj] = fma2(hi[ii].x, hj[jj].x, acc[ii][jj]);
                        acc[ii][jj] = fma2(hi[ii].y, hj[jj].y, acc[ii][jj]);
                    }
            }
            #pragma unroll
            for (int ii = 0; ii < 4; ii++) {
                const int i = r0 + ii, o = a64(i, cq0);
                const float hgv = sHg[i], omh = 1.0f - hgv, sc = hgv * (1.0f / 64.0f);
                float4 e = *reinterpret_cast<const float4*>(sHeb + o);
                float v[4];
                #pragma unroll
                for (int jj = 0; jj < 4; jj++) { float pa, pb; up2(acc[ii][jj], pa, pb); v[jj] = pa + pb; }
                v[0] = omh * e.x + sc * v[0]; v[1] = omh * e.y + sc * v[1];
                v[2] = omh * e.z + sc * v[2]; v[3] = omh * e.w + sc * v[3];
                #pragma unroll
                for (int jj = 0; jj < 4; jj++) if (i == c0 + jj) v[jj] = 0.0f;
                *reinterpret_cast<float4*>(sHeb + o) = make_float4(v[0], v[1], v[2], v[3]);
            }
        }
        if (tid < 64) sDecW[tid] *= sOmWg[tid];
        __syncthreads();
    }
}

extern "C" void kernel_launch(void* const* d_in, const int* in_sizes, int n_in,
                              void* d_out, int out_size) {
    const float* x    = (const float*)d_in[0];
    const float* h0   = (const float*)d_in[1];
    const float* W0   = (const float*)d_in[2];
    const float* heb0 = (const float*)d_in[3];
    const float* nid  = (const float*)d_in[4];
    const float* w1   = (const float*)d_in[5];
    const float* b1   = (const float*)d_in[6];
    const float* w2   = (const float*)d_in[7];
    const float* b2   = (const float*)d_in[8];
    const float* injw = (const float*)d_in[9];
    const float* injb = (const float*)d_in[10];
    const float* wdl  = (const float*)d_in[11];
    const float* dgl  = (const float*)d_in[12];
    const float* hdl  = (const float*)d_in[13];
    const int*   ipi  = (const int*)d_in[14];
    const int*   opi  = (const int*)d_in[15];
    float* out = (float*)d_out;

    const int smem_bytes = (4096 * 4 + 8192 + 64 * 4 + 128 + 64) * 4;
    cudaFuncSetAttribute(mg_main, cudaFuncAttributeMaxDynamicSharedMemorySize, smem_bytes);

    mg_transpose<<<32, 256>>>(w1, w2);
    mg_inject<<<NCc, 256>>>(x, injw, injb);
    mg_main<<<NCc * Bsz, 256, smem_bytes>>>(h0, W0, heb0, nid, wdl, dgl, hdl,
                                            b1, b2, ipi, opi, out);
}

// round 10
// speedup vs baseline: 1.9571x; 1.0548x over previous
#include <cuda_runtime.h>
#include <math.h>

#define Bsz 8
#define Tt  16
#define NCc 128

typedef unsigned long long u64;

__device__ __align__(16) float g_w1T[64 * 128];
__device__ __align__(16) float g_w2T[128 * 64];
__device__ __align__(16) float g_inj[Bsz * Tt * NCc * 256];

// Prep: transpose MLP weights + precompute inj[b,t,c,k]. grid=128, block=256.
__global__ __launch_bounds__(256) void mg_prep(const float* __restrict__ x,
                                               const float* __restrict__ injw,
                                               const float* __restrict__ injb,
                                               const float* __restrict__ w1,
                                               const float* __restrict__ w2) {
    const int c = blockIdx.x, k = threadIdx.x;
    const int idx = c * 256 + k;
    if (idx < 8192) {
        int h = idx / 64, d = idx % 64;
        g_w1T[d * 128 + h] = w1[idx];
        int d2 = idx / 128, h2 = idx % 128;
        g_w2T[h2 * 64 + d2] = w2[idx];
    }
    __shared__ float sx[64];
    float4 wv[16];
    const float4* wrow = reinterpret_cast<const float4*>(injw + (long)(c * 256 + k) * 64);
    #pragma unroll
    for (int q = 0; q < 16; q++) wv[q] = __ldg(wrow + q);
    const float bias = injb[c * 256 + k];
    for (int bt = 0; bt < Bsz * Tt; bt++) {
        if (k < 64) sx[k] = x[((long)bt * NCc + c) * 64 + k];
        __syncthreads();
        float acc = bias;
        #pragma unroll
        for (int q = 0; q < 16; q++) {
            float4 xv = *reinterpret_cast<const float4*>(sx + 4 * q);
            acc = fmaf(wv[q].x, xv.x, acc); acc = fmaf(wv[q].y, xv.y, acc);
            acc = fmaf(wv[q].z, xv.z, acc); acc = fmaf(wv[q].w, xv.w, acc);
        }
        g_inj[((long)bt * NCc + c) * 256 + k] = acc;
        __syncthreads();
    }
}

__device__ __forceinline__ u64 dup2(float a) {
    u64 r; asm("mov.b64 %0, {%1, %1};" : "=l"(r) : "r"(__float_as_uint(a))); return r;
}
__device__ __forceinline__ u64 fma2(u64 a, u64 b, u64 c) {
    u64 d; asm("fma.rn.f32x2 %0, %1, %2, %3;" : "=l"(d) : "l"(a), "l"(b), "l"(c)); return d;
}
__device__ __forceinline__ void up2(u64 v, float& a, float& b) {
    unsigned int x, y; asm("mov.b64 {%0, %1}, %2;" : "=r"(x), "=r"(y) : "l"(v));
    a = __uint_as_float(x); b = __uint_as_float(y);
}

// XOR chunk swizzle (16B chunks permuted per row)
__device__ __forceinline__ int pr(int r)           { return (r ^ (r >> 3)) & 7; }
__device__ __forceinline__ int a64(int r, int cq)  { return (r << 6) + ((cq ^ pr(r)) << 2); }
__device__ __forceinline__ int a64s(int r, int c)  { return (r << 6) + (((c >> 2) ^ pr(r)) << 2) + (c & 3); }
__device__ __forceinline__ int a128(int r, int cq) { return (r << 7) + ((cq ^ pr(r)) << 2); }

__global__ __launch_bounds__(256, 2)
void mg_main(const float* __restrict__ h0,    const float* __restrict__ W0,
             const float* __restrict__ heb0,  const float* __restrict__ nid,
             const float* __restrict__ wdl,   const float* __restrict__ dgl,
             const float* __restrict__ hdl,   const float* __restrict__ b1g,
             const float* __restrict__ b2g,
             const int*   __restrict__ ipi,   const int*   __restrict__ opi,
             float* __restrict__ out) {
    extern __shared__ float sm[];
    float* sH    = sm;               // 4096 (a64 swizzled)
    float* sW0   = sH    + 4096;
    float* sHeb  = sW0   + 4096;
    float* sM    = sHeb  + 4096;
    float* sBuf  = sM    + 4096;     // 8192: Wh (a64) then hidden (a128)
    float* sGam  = sBuf  + 8192;     // 64
    float* sHg   = sGam  + 64;
    float* sOmWg = sHg   + 64;
    float* sDecW = sOmWg + 64;
    float* sB1   = sDecW + 64;       // 128
    float* sB2   = sB1   + 128;      // 64
    __shared__ int sIp[4], sOp[4];

    const int tid = threadIdx.x;
    const int c   = blockIdx.x / Bsz;
    const int b   = blockIdx.x % Bsz;
    const long base = (long)(b * NCc + c) * 4096;

    if (tid < 64) {
        sGam[tid]  = 0.5f / (1.0f + expf(-dgl[c * 64 + tid]));
        sHg[tid]   = 0.5f / (1.0f + expf(-hdl[c * 64 + tid]));
        sOmWg[tid] = 1.0f - 0.5f / (1.0f + expf(-wdl[c * 64 + tid]));
        sDecW[tid] = 1.0f;           // pw for the NEXT Wh build (t=1) set in P5a of t=0
        sB2[tid]   = b2g[tid];
    }
    if (tid < 128) sB1[tid] = b1g[tid];
    if (tid < 4) { sIp[tid] = ipi[c * 4 + tid]; sOp[tid] = opi[c * 4 + tid]; }
    for (int k = tid; k < 1024; k += 256) {       // swizzled fill
        const int r = k >> 4, cq = k & 15, so = a64(r, cq);
        const long go = base + ((long)k << 2);
        *reinterpret_cast<float4*>(sH   + so) = __ldg(reinterpret_cast<const float4*>(h0   + go));
        *reinterpret_cast<float4*>(sW0  + so) = __ldg(reinterpret_cast<const float4*>(W0   + go));
        *reinterpret_cast<float4*>(sHeb + so) = __ldg(reinterpret_cast<const float4*>(heb0 + go));
    }
    __syncthreads();

    // ===== P0 (t=0 only): Wh = W0 + heb; scatter inj(t=0) =====
    for (int k = tid; k < 1024; k += 256) {
        const int o = k << 2;
        float4 w = *reinterpret_cast<const float4*>(sW0 + o);
        float4 hb = *reinterpret_cast<const float4*>(sHeb + o);
        *reinterpret_cast<float4*>(sBuf + o) = make_float4(w.x + hb.x, w.y + hb.y, w.z + hb.z, w.w + hb.w);
    }
    if (tid < 64) {
        const long ib = ((long)(b * Tt) * NCc + c) * 256 + tid;
        #pragma unroll
        for (int a = 0; a < 4; a++)
            sH[a64s(sIp[a], tid)] += __ldg(g_inj + ib + a * 64);
    }
    __syncthreads();

    // warp-block mapping
    const int wid = tid >> 5, lane = tid & 31;
    const int lr = lane >> 2, lc = lane & 3;
    const int r0   = (wid & 1) * 32 + lr * 4;
    const int cb   = (wid >> 1) * 16;
    const int c0   = cb + lc * 4;
    const int cq0  = c0 >> 2;
    const int p3c0 = (wid >> 1) * 32 + lc * 8;
    const int p3cq = p3c0 >> 2;

    for (int t = 0; t < Tt; ++t) {
        // ===== P2: m = Wh @ h_in (4x4 tiles) =====
        {
            u64 acc[4][2];
            #pragma unroll
            for (int ii = 0; ii < 4; ii++) { acc[ii][0] = acc[ii][1] = 0ULL; }
            #pragma unroll 4
            for (int j = 0; j < 64; j += 4) {
                float4 wr[4]; ulonglong2 hv[4];
                #pragma unroll
                for (int ii = 0; ii < 4; ii++)
                    wr[ii] = *reinterpret_cast<const float4*>(sBuf + a64(r0 + ii, j >> 2));
                #pragma unroll
                for (int jj = 0; jj < 4; jj++)
                    hv[jj] = *reinterpret_cast<const ulonglong2*>(sH + a64(j + jj, cq0));
                #pragma unroll
                for (int ii = 0; ii < 4; ii++) {
                    const float* wf = reinterpret_cast<const float*>(&wr[ii]);
                    #pragma unroll
                    for (int jj = 0; jj < 4; jj++) {
                        u64 wd = dup2(wf[jj]);
                        acc[ii][0] = fma2(wd, hv[jj].x, acc[ii][0]);
                        acc[ii][1] = fma2(wd, hv[jj].y, acc[ii][1]);
                    }
                }
            }
            #pragma unroll
            for (int ii = 0; ii < 4; ii++) {
                ulonglong2 v; v.x = acc[ii][0]; v.y = acc[ii][1];
                *reinterpret_cast<ulonglong2*>(sM + a64(r0 + ii, cq0)) = v;
            }
        }
        __syncthreads();

        // ===== P3: hidden = tanh(m @ w1T + b1), double-buffered weight prefetch =====
        {
            u64 acc[4][4];
            #pragma unroll
            for (int ii = 0; ii < 4; ii++) { acc[ii][0]=acc[ii][1]=acc[ii][2]=acc[ii][3]=0ULL; }
            ulonglong2 wA[2][4], wB[2][4];
            #pragma unroll
            for (int dd = 0; dd < 4; dd++) {
                wA[0][dd] = __ldg(reinterpret_cast<const ulonglong2*>(g_w1T + dd * 128 + p3c0));
                wB[0][dd] = __ldg(reinterpret_cast<const ulonglong2*>(g_w1T + dd * 128 + p3c0 + 4));
            }
            #pragma unroll
            for (int k = 0; k < 16; k++) {
                const int cur = k & 1, nxt = cur ^ 1;
                if (k < 15) {
                    const int d2 = (k + 1) * 4;
                    #pragma unroll
                    for (int dd = 0; dd < 4; dd++) {
                        wA[nxt][dd] = __ldg(reinterpret_cast<const ulonglong2*>(g_w1T + (d2 + dd) * 128 + p3c0));
                        wB[nxt][dd] = __ldg(reinterpret_cast<const ulonglong2*>(g_w1T + (d2 + dd) * 128 + p3c0 + 4));
                    }
                }
                const int d = k * 4;
                float4 mv[4];
                #pragma unroll
                for (int ii = 0; ii < 4; ii++)
                    mv[ii] = *reinterpret_cast<const float4*>(sM + a64(r0 + ii, d >> 2));
                #pragma unroll
                for (int ii = 0; ii < 4; ii++) {
                    const float* mf = reinterpret_cast<const float*>(&mv[ii]);
                    #pragma unroll
                    for (int dd = 0; dd < 4; dd++) {
                        u64 md = dup2(mf[dd]);
                        acc[ii][0] = fma2(md, wA[cur][dd].x, acc[ii][0]);
                        acc[ii][1] = fma2(md, wA[cur][dd].y, acc[ii][1]);
                        acc[ii][2] = fma2(md, wB[cur][dd].x, acc[ii][2]);
                        acc[ii][3] = fma2(md, wB[cur][dd].y, acc[ii][3]);
                    }
                }
            }
            #pragma unroll
            for (int ii = 0; ii < 4; ii++) {
                const int r = r0 + ii;
                float v[8];
                up2(acc[ii][0], v[0], v[1]); up2(acc[ii][1], v[2], v[3]);
                up2(acc[ii][2], v[4], v[5]); up2(acc[ii][3], v[6], v[7]);
                float4 o0, o1;
                o0.x = tanhf(v[0] + sB1[p3c0 + 0]); o0.y = tanhf(v[1] + sB1[p3c0 + 1]);
                o0.z = tanhf(v[2] + sB1[p3c0 + 2]); o0.w = tanhf(v[3] + sB1[p3c0 + 3]);
                o1.x = tanhf(v[4] + sB1[p3c0 + 4]); o1.y = tanhf(v[5] + sB1[p3c0 + 5]);
                o1.z = tanhf(v[6] + sB1[p3c0 + 6]); o1.w = tanhf(v[7] + sB1[p3c0 + 7]);
                *reinterpret_cast<float4*>(sBuf + a128(r, p3cq))     = o0;
                *reinterpret_cast<float4*>(sBuf + a128(r, p3cq + 1)) = o1;
            }
        }
        __syncthreads();

        // ===== P4: MLP2 + gated update, double-buffered weight prefetch =====
        {
            u64 acc[4][2];
            #pragma unroll
            for (int ii = 0; ii < 4; ii++) { acc[ii][0] = acc[ii][1] = 0ULL; }
            ulonglong2 wv[2][4];
            #pragma unroll
            for (int hh = 0; hh < 4; hh++)
                wv[0][hh] = __ldg(reinterpret_cast<const ulonglong2*>(g_w2T + hh * 64 + c0));
            #pragma unroll
            for (int k = 0; k < 32; k++) {
                const int cur = k & 1, nxt = cur ^ 1;
                if (k < 31) {
                    const int h2 = (k + 1) * 4;
                    #pragma unroll
                    for (int hh = 0; hh < 4; hh++)
                        wv[nxt][hh] = __ldg(reinterpret_cast<const ulonglong2*>(g_w2T + (h2 + hh) * 64 + c0));
                }
                const int h = k * 4;
                float4 tv[4];
                #pragma unroll
                for (int ii = 0; ii < 4; ii++)
                    tv[ii] = *reinterpret_cast<const float4*>(sBuf + a128(r0 + ii, h >> 2));
                #pragma unroll
                for (int ii = 0; ii < 4; ii++) {
                    const float* tf = reinterpret_cast<const float*>(&tv[ii]);
                    #pragma unroll
                    for (int hh = 0; hh < 4; hh++) {
                        u64 td = dup2(tf[hh]);
                        acc[ii][0] = fma2(td, wv[cur][hh].x, acc[ii][0]);
                        acc[ii][1] = fma2(td, wv[cur][hh].y, acc[ii][1]);
                    }
                }
            }
            #pragma unroll
            for (int ii = 0; ii < 4; ii++) {
                const int i = r0 + ii, o = a64(i, cq0);
                const float g = sGam[i], omg = 1.0f - g;
                float4 nv = __ldg(reinterpret_cast<const float4*>(nid + ((long)c * 64 + i) * 64 + c0));
                float v[4];
                up2(acc[ii][0], v[0], v[1]); up2(acc[ii][1], v[2], v[3]);
                float4 hc = *reinterpret_cast<const float4*>(sH + o);
                float4 ov;
                ov.x = omg * hc.x + g * tanhf(v[0] + sB2[c0 + 0] + nv.x);
                ov.y = omg * hc.y + g * tanhf(v[1] + sB2[c0 + 1] + nv.y);
                ov.z = omg * hc.z + g * tanhf(v[2] + sB2[c0 + 2] + nv.z);
                ov.w = omg * hc.w + g * tanhf(v[3] + sB2[c0 + 3] + nv.w);
                *reinterpret_cast<float4*>(sH + o) = ov;
            }
        }
        __syncthreads();

        // ===== P5a: readout + gram (reads h_new) + decay update =====
        if (tid < 64) {
            float s = sH[a64s(sOp[0], tid)] + sH[a64s(sOp[1], tid)]
                    + sH[a64s(sOp[2], tid)] + sH[a64s(sOp[3], tid)];
            out[((long)(b * Tt + t) * NCc + c) * 64 + tid] = s * 0.125f;
            sDecW[tid] *= sOmWg[tid];      // pw for step t+1 (no reader until P5b)
        }
        u64 acc5[4][4];
        {
            #pragma unroll
            for (int ii = 0; ii < 4; ii++) { acc5[ii][0]=acc5[ii][1]=acc5[ii][2]=acc5[ii][3]=0ULL; }
            #pragma unroll 4
            for (int dq = 0; dq < 64; dq += 4) {
                ulonglong2 hi[4], hj[4];
                #pragma unroll
                for (int ii = 0; ii < 4; ii++)
                    hi[ii] = *reinterpret_cast<const ulonglong2*>(sH + a64(r0 + ii, dq >> 2));
                #pragma unroll
                for (int jj = 0; jj < 4; jj++)
                    hj[jj] = *reinterpret_cast<const ulonglong2*>(sH + a64(c0 + jj, dq >> 2));
                #pragma unroll
                for (int ii = 0; ii < 4; ii++)
                    #pragma unroll
                    for (int jj = 0; jj < 4; jj++) {
                        acc5[ii][jj] = fma2(hi[ii].x, hj[jj].x, acc5[ii][jj]);
                        acc5[ii][jj] = fma2(hi[ii].y, hj[jj].y, acc5[ii][jj]);
                    }
            }
        }
        __syncthreads();

        // ===== P5b: heb store + next Wh build + scatter inj(t+1) =====
        {
            const bool more = (t + 1 < Tt);
            #pragma unroll
            for (int ii = 0; ii < 4; ii++) {
                const int i = r0 + ii, o = a64(i, cq0);
                const float hgv = sHg[i], omh = 1.0f - hgv, sc = hgv * (1.0f / 64.0f);
                float4 e = *reinterpret_cast<const float4*>(sHeb + o);
                float v[4];
                #pragma unroll
                for (int jj = 0; jj < 4; jj++) { float pa, pb; up2(acc5[ii][jj], pa, pb); v[jj] = pa + pb; }
                v[0] = omh * e.x + sc * v[0]; v[1] = omh * e.y + sc * v[1];
                v[2] = omh * e.z + sc * v[2]; v[3] = omh * e.w + sc * v[3];
                #pragma unroll
                for (int jj = 0; jj < 4; jj++) if (i == c0 + jj) v[jj] = 0.0f;
                float4 hn = make_float4(v[0], v[1], v[2], v[3]);
                *reinterpret_cast<float4*>(sHeb + o) = hn;
                if (more) {
                    const float pwn = sDecW[i];
                    float4 w = *reinterpret_cast<const float4*>(sW0 + o);
                    float4 wh;
                    wh.x = fmaf(pwn, w.x, hn.x); wh.y = fmaf(pwn, w.y, hn.y);
                    wh.z = fmaf(pwn, w.z, hn.z); wh.w = fmaf(pwn, w.w, hn.w);
                    *reinterpret_cast<float4*>(sBuf + o) = wh;
                }
            }
            if (more && tid < 64) {
                const long ib = ((long)(b * Tt + t + 1) * NCc + c) * 256 + tid;
                #pragma unroll
                for (int a = 0; a < 4; a++)
                    sH[a64s(sIp[a], tid)] += __ldg(g_inj + ib + a * 64);
            }
        }
        __syncthreads();
    }
}

extern "C" void kernel_launch(void* const* d_in, const int* in_sizes, int n_in,
                              void* d_out, int out_size) {
    const float* x    = (const float*)d_in[0];
    const float* h0   = (const float*)d_in[1];
    const float* W0   = (const float*)d_in[2];
    const float* heb0 = (const float*)d_in[3];
    const float* nid  = (const float*)d_in[4];
    const float* w1   = (const float*)d_in[5];
    const float* b1   = (const float*)d_in[6];
    const float* w2   = (const float*)d_in[7];
    const float* b2   = (const float*)d_in[8];
    const float* injw = (const float*)d_in[9];
    const float* injb = (const float*)d_in[10];
    const float* wdl  = (const float*)d_in[11];
    const float* dgl  = (const float*)d_in[12];
    const float* hdl  = (const float*)d_in[13];
    const int*   ipi  = (const int*)d_in[14];
    const int*   opi  = (const int*)d_in[15];
    float* out = (float*)d_out;

    const int smem_bytes = (4096 * 4 + 8192 + 64 * 4 + 128 + 64) * 4;
    cudaFuncSetAttribute(mg_main, cudaFuncAttributeMaxDynamicSharedMemorySize, smem_bytes);

    mg_prep<<<NCc, 256>>>(x, injw, injb, w1, w2);
    mg_main<<<NCc * Bsz, 256, smem_bytes>>>(h0, W0, heb0, nid, wdl, dgl, hdl,
                                            b1, b2, ipi, opi, out);
}